// round 13
// baseline (speedup 1.0000x reference)
#include <cuda_runtime.h>
#include <cuda_fp16.h>
#include <cstdint>

#define Nn 100000
#define Mm 800000
#define CAP 48
#define SPLIT 50048   // multiple of 32; A=[0,SPLIT), B=[SPLIT,Nn)

// ---------------- device scratch (no allocations allowed) ----------------
__device__ __half    g_h2h[(size_t)Nn * 64];    // h2 rows fp16 (identity col order)
__device__ __half    g_xh[(size_t)Nn * 64];     // x rows fp16 (identity col order)
__device__ uint32_t  g_aggEh[(size_t)Nn * 32];  // fp16 aggE rows; words 24..31 pad
__device__ int       g_cur[Nn];                 // packed: tot(10)|c1(10)|c2(10)
__device__ int       g_slots[(size_t)Nn * CAP]; // src node per bucket slot
__device__ int       g_ovf_cnt;
__device__ int2      g_ovf[8192];               // overflow: (src, dst)

__device__ __forceinline__ void red_add_h8(uint32_t* p, uint32_t a, uint32_t b,
                                           uint32_t c, uint32_t d) {
    asm volatile("red.global.add.noftz.v4.f16x2 [%0], {%1,%2,%3,%4};"
                 :: "l"(p), "r"(a), "r"(b), "r"(c), "r"(d) : "memory");
}

__device__ __forceinline__ void mma_f16(float c[4], uint32_t a0, uint32_t a1,
                                        uint32_t a2, uint32_t a3,
                                        uint32_t b0, uint32_t b1) {
    asm volatile(
        "mma.sync.aligned.m16n8k16.row.col.f32.f16.f16.f32 "
        "{%0,%1,%2,%3},{%4,%5,%6,%7},{%8,%9},{%0,%1,%2,%3};"
        : "+f"(c[0]), "+f"(c[1]), "+f"(c[2]), "+f"(c[3])
        : "r"(a0), "r"(a1), "r"(a2), "r"(a3), "r"(b0), "r"(b1));
}

__device__ __forceinline__ uint32_t pack_h2(float a, float b) {
    __half2 h = __floats2half2_rn(a, b);
    return *(uint32_t*)&h;
}

// ---------------- kernels ----------------

__global__ void zero_kernel() {
    int gid = blockIdx.x * blockDim.x + threadIdx.x;
    int stride = gridDim.x * blockDim.x;
    uint4 z = make_uint4(0u, 0u, 0u, 0u);
    uint4* a4 = (uint4*)g_aggEh;
    for (int i = gid; i < Nn * 8; i += stride) a4[i] = z;
    for (int i = gid; i < Nn; i += stride) g_cur[i] = 0;
    if (gid == 0) g_ovf_cnt = 0;
}

// 2 threads/edge: fp16x8 red into aggE row + packed cursor + bucket fill
__global__ void edge_scatter_kernel(const float* __restrict__ ef,
                                    const int* __restrict__ esrc,
                                    const int* __restrict__ edst,
                                    const int* __restrict__ etype) {
    int gid = blockIdx.x * blockDim.x + threadIdx.x;
    int e = gid >> 1, q = gid & 1;
    if (e >= Mm) return;
    int dst = edst[e];
    int t   = etype[e];
    const float4* ef4 = (const float4*)ef;
    float4 v0 = ef4[e * 4 + q * 2];
    float4 v1 = ef4[e * 4 + q * 2 + 1];
    uint32_t h0 = pack_h2(v0.x, v0.y), h1 = pack_h2(v0.z, v0.w);
    uint32_t h2 = pack_h2(v1.x, v1.y), h3 = pack_h2(v1.z, v1.w);
    red_add_h8(g_aggEh + (size_t)dst * 32 + t * 8 + q * 4, h0, h1, h2, h3);
    if (q == 0) {
        int inc = 1 + ((t == 1) ? (1 << 10) : 0) + ((t == 2) ? (1 << 20) : 0);
        int old = atomicAdd(&g_cur[dst], inc);
        int p = old & 1023;
        int src = esrc[e];
        if (p < CAP) {
            g_slots[(size_t)dst * CAP + p] = src;
        } else {
            int o = atomicAdd(&g_ovf_cnt, 1);
            if (o < 8192) g_ovf[o] = make_int2(src, dst);
        }
    }
}

// h2 GEMM (side stream): A = [x*(t==0) | x*(t==1)] k=128, fp32 x via float4,
// own fragment permutation. Writes h2h (fp16) AND x as fp16 (g_xh).
__global__ __launch_bounds__(256, 2)
void h2_gemm_kernel(const float* __restrict__ x,
                    const int* __restrict__ ntype,
                    const float* __restrict__ W2, const float* __restrict__ b2) {
    extern __shared__ uint32_t smu[];
    uint4* Wf = (uint4*)smu;                 // [8][4][32] uint4 = 16 KB
    float* bc = (float*)(smu + 4096);        // [128]

    const int tid = threadIdx.x;
    const int w = tid >> 5, lane = tid & 31;
    const int g = lane >> 2, tq = lane & 3;

    for (int idx = tid; idx < 1024; idx += 256) {
        int ln = idx & 31;
        int ntp = (idx >> 5) & 3;
        int kb = idx >> 7;                    // 0..7
        int tqf = ln & 3, gf = ln >> 2;
        int ty = kb >> 2, p = kb & 3;
        int col0 = (2 * ntp) * 8 + gf;
        int col1 = col0 + 8;
        auto wv2 = [&](int h, int outc) -> uint32_t {
            int ca = 16 * p + 4 * tqf + 2 * h;
            return pack_h2(W2[(size_t)ty * 4096 + ca * 64 + outc],
                           W2[(size_t)ty * 4096 + (ca + 1) * 64 + outc]);
        };
        uint4 wv;
        wv.x = wv2(0, col0); wv.y = wv2(1, col0);
        wv.z = wv2(0, col1); wv.w = wv2(1, col1);
        Wf[idx] = wv;
    }
    if (tid < 128) bc[tid] = b2[tid];
    __syncthreads();

    const int G = Nn >> 4;
    const int nwarps = gridDim.x << 3;
    __half2* h2p = (__half2*)g_h2h;
    uint32_t* xh32 = (uint32_t*)g_xh;
    const float4* xp4 = (const float4*)x;

    for (int grp = blockIdx.x * 8 + w; grp < G; grp += nwarps) {
        int base = grp << 4;
        uint32_t xw[2][8], msk[2];
        int tt[2];
        #pragma unroll
        for (int j = 0; j < 2; j++) {
            int node = base + g + 8 * j;
            tt[j] = __ldg(&ntype[node]);
            msk[j] = (tt[j] == 0) ? 0xFFFFFFFFu : 0u;
            #pragma unroll
            for (int m = 0; m < 4; m++) {
                float4 f = xp4[(size_t)node * 16 + 4 * m + tq];
                xw[j][2 * m]     = pack_h2(f.x, f.y);
                xw[j][2 * m + 1] = pack_h2(f.z, f.w);
            }
        }

        float acc[8][4];
        #pragma unroll
        for (int nt = 0; nt < 8; nt++)
            #pragma unroll
            for (int jj = 0; jj < 4; jj++) acc[nt][jj] = 0.f;

        #pragma unroll
        for (int kb = 0; kb < 8; kb++) {
            int p = kb & 3;
            uint32_t s0 = (kb < 4) ? msk[0] : ~msk[0];
            uint32_t s1 = (kb < 4) ? msk[1] : ~msk[1];
            uint32_t a0 = xw[0][2 * p] & s0;
            uint32_t a2 = xw[0][2 * p + 1] & s0;
            uint32_t a1 = xw[1][2 * p] & s1;
            uint32_t a3 = xw[1][2 * p + 1] & s1;
            #pragma unroll
            for (int ntp = 0; ntp < 4; ntp++) {
                uint4 bw = Wf[(kb * 4 + ntp) * 32 + lane];
                mma_f16(acc[2 * ntp], a0, a1, a2, a3, bw.x, bw.y);
                mma_f16(acc[2 * ntp + 1], a0, a1, a2, a3, bw.z, bw.w);
            }
        }

        #pragma unroll
        for (int j = 0; j < 2; j++) {
            int node = base + g + 8 * j;
            int t = tt[j];
            uint2* xdst = (uint2*)(xh32 + (size_t)node * 32);
            #pragma unroll
            for (int m = 0; m < 4; m++)
                xdst[(8 * m + 2 * tq) >> 1] = make_uint2(xw[j][2 * m], xw[j][2 * m + 1]);
            #pragma unroll
            for (int nt = 0; nt < 8; nt++) {
                int col0 = nt * 8 + 2 * tq;
                float v0 = acc[nt][2 * j + 0] + bc[t * 64 + col0];
                float v1 = acc[nt][2 * j + 1] + bc[t * 64 + col0 + 1];
                h2p[(size_t)node * 32 + nt * 4 + tq] = __floats2half2_rn(v0, v1);
            }
        }
    }
}

// h1 GEMM over node range [begin, begin+count), count % 16 == 0.
// rmw=0: full write; rmw=1: out += result.
__global__ __launch_bounds__(256, 2)
void h1_gemm_kernel(const int* __restrict__ ntype,
                    const float* __restrict__ W1, const float* __restrict__ b1,
                    const float* __restrict__ W5, const float* __restrict__ b5,
                    float* __restrict__ out, int begin, int count, int rmw) {
    extern __shared__ uint32_t smu[];
    uint4* Wf = (uint4*)smu;                 // [12][4][32] uint4 = 24 KB
    float* bc = (float*)(smu + 6144);        // [128]

    const int tid = threadIdx.x;
    const int w = tid >> 5, lane = tid & 31;
    const int g = lane >> 2, tq = lane & 3;

    for (int idx = tid; idx < 1536; idx += 256) {
        int ln = idx & 31;
        int ntp = (idx >> 5) & 3;
        int kb = idx >> 7;                    // 0..11
        int tqf = ln & 3, gf = ln >> 2;
        int col0 = (2 * ntp) * 8 + gf;
        int col1 = col0 + 8;
        auto val = [&](int h, int elem, int outc) -> float {
            if (kb < 8) {
                int ty = kb >> 2, p = kb & 3;
                int wd = 16 * (p >> 1) + 4 * tqf + 2 * (p & 1) + h;
                int hh = 2 * wd + elem;
                return W1[(size_t)ty * 4096 + hh * 64 + outc];
            } else {
                int p = kb - 8;
                int wd = 16 * (p >> 1) + 4 * tqf + 2 * (p & 1) + h;
                if (wd < 24) {
                    int t = wd >> 3, colf = 2 * (wd & 7) + elem;
                    return W5[(size_t)(t * 16 + colf) * 64 + outc];
                }
                if (wd == 24) return b5[elem * 64 + outc];
                if (wd == 25) return (elem == 0) ? b5[128 + outc] : 0.f;
                return 0.f;
            }
        };
        uint4 wv;
        wv.x = pack_h2(val(0, 0, col0), val(0, 1, col0));
        wv.y = pack_h2(val(1, 0, col0), val(1, 1, col0));
        wv.z = pack_h2(val(0, 0, col1), val(0, 1, col1));
        wv.w = pack_h2(val(1, 0, col1), val(1, 1, col1));
        Wf[idx] = wv;
    }
    if (tid < 128) bc[tid] = b1[tid];
    __syncthreads();

    const int G = count >> 4;
    const int nwarps = gridDim.x << 3;
    float2* outp = (float2*)out;
    const uint4* xh4 = (const uint4*)g_xh;
    const uint4* ag4 = (const uint4*)g_aggEh;

    for (int grp = blockIdx.x * 8 + w; grp < G; grp += nwarps) {
        int base = begin + (grp << 4);
        uint4 xu[2][2], tu[2][2];
        uint32_t msk[2];
        int tt[2];
        #pragma unroll
        for (int j = 0; j < 2; j++) {
            int node = base + g + 8 * j;
            tt[j] = __ldg(&ntype[node]);
            msk[j] = (tt[j] == 0) ? 0xFFFFFFFFu : 0u;
            xu[j][0] = __ldg(&xh4[(size_t)node * 8 + tq]);
            xu[j][1] = __ldg(&xh4[(size_t)node * 8 + tq + 4]);
            tu[j][0] = __ldg(&ag4[(size_t)node * 8 + tq]);
            tu[j][1] = __ldg(&ag4[(size_t)node * 8 + tq + 4]);
            int cv = __ldg(&g_cur[node]);
            if (tq == 2) {
                int tot = cv & 1023, c1i = (cv >> 10) & 1023, c2i = cv >> 20;
                tu[j][1].x = pack_h2((float)(tot - c1i - c2i), (float)c1i);
                tu[j][1].y = pack_h2((float)c2i, 0.f);
            }
        }

        float acc[8][4];
        #pragma unroll
        for (int nt = 0; nt < 8; nt++)
            #pragma unroll
            for (int jj = 0; jj < 4; jj++) acc[nt][jj] = 0.f;

        auto slot = [&](uint4 uq[2], int p, int h) -> uint32_t {
            uint4 uu = uq[p >> 1];
            return (p & 1) ? (h ? uu.w : uu.z) : (h ? uu.y : uu.x);
        };

        #pragma unroll
        for (int kb = 0; kb < 12; kb++) {
            uint32_t a0, a1, a2, a3;
            if (kb < 8) {
                int p = kb & 3;
                uint32_t s0 = (kb < 4) ? msk[0] : ~msk[0];
                uint32_t s1 = (kb < 4) ? msk[1] : ~msk[1];
                a0 = slot(xu[0], p, 0) & s0;
                a2 = slot(xu[0], p, 1) & s0;
                a1 = slot(xu[1], p, 0) & s1;
                a3 = slot(xu[1], p, 1) & s1;
            } else {
                int p = kb - 8;
                a0 = slot(tu[0], p, 0); a2 = slot(tu[0], p, 1);
                a1 = slot(tu[1], p, 0); a3 = slot(tu[1], p, 1);
            }
            #pragma unroll
            for (int ntp = 0; ntp < 4; ntp++) {
                uint4 bw = Wf[(kb * 4 + ntp) * 32 + lane];
                mma_f16(acc[2 * ntp], a0, a1, a2, a3, bw.x, bw.y);
                mma_f16(acc[2 * ntp + 1], a0, a1, a2, a3, bw.z, bw.w);
            }
        }

        #pragma unroll
        for (int j = 0; j < 2; j++) {
            int node = base + g + 8 * j;
            int t = tt[j];
            #pragma unroll
            for (int nt = 0; nt < 8; nt++) {
                int col0 = nt * 8 + 2 * tq;
                float v0 = acc[nt][2 * j + 0] + bc[t * 64 + col0];
                float v1 = acc[nt][2 * j + 1] + bc[t * 64 + col0 + 1];
                size_t oidx = (size_t)node * 32 + nt * 4 + tq;
                if (rmw) {
                    float2 o = outp[oidx];
                    o.x += v0; o.y += v1;
                    outp[oidx] = o;
                } else {
                    outp[oidx] = make_float2(v0, v1);
                }
            }
        }
    }
}

// Bucket gather over [begin, begin+count): rmw=0 full write, rmw=1 out +=.
__global__ __launch_bounds__(256)
void gatherH_kernel(float* __restrict__ out, int begin, int count, int rmw) {
    int tid = threadIdx.x;
    int node = begin + blockIdx.x * 32 + (tid >> 3);
    int q = tid & 7;
    if (node >= begin + count) return;
    int deg = g_cur[node] & 1023;
    if (deg > CAP) deg = CAP;
    if (deg == 0 && rmw) return;

    const uint4* H = (const uint4*)g_h2h;
    const int* sl = &g_slots[(size_t)node * CAP];
    float acc[8];
    #pragma unroll
    for (int u = 0; u < 8; u++) acc[u] = 0.f;

    auto add8 = [&](uint4 hv) {
        float2 f0 = __half22float2(*(__half2*)&hv.x);
        float2 f1 = __half22float2(*(__half2*)&hv.y);
        float2 f2 = __half22float2(*(__half2*)&hv.z);
        float2 f3 = __half22float2(*(__half2*)&hv.w);
        acc[0] += f0.x; acc[1] += f0.y; acc[2] += f1.x; acc[3] += f1.y;
        acc[4] += f2.x; acc[5] += f2.y; acc[6] += f3.x; acc[7] += f3.y;
    };

    int i = 0;
    for (; i + 8 <= deg; i += 8) {
        int s[8];
        #pragma unroll
        for (int u = 0; u < 8; u++) s[u] = __ldg(&sl[i + u]);
        uint4 v[8];
        #pragma unroll
        for (int u = 0; u < 8; u++) v[u] = __ldg(&H[(size_t)s[u] * 8 + q]);
        #pragma unroll
        for (int u = 0; u < 8; u++) add8(v[u]);
    }
    for (; i + 4 <= deg; i += 4) {
        int s[4];
        #pragma unroll
        for (int u = 0; u < 4; u++) s[u] = __ldg(&sl[i + u]);
        uint4 v[4];
        #pragma unroll
        for (int u = 0; u < 4; u++) v[u] = __ldg(&H[(size_t)s[u] * 8 + q]);
        #pragma unroll
        for (int u = 0; u < 4; u++) add8(v[u]);
    }
    for (; i < deg; i++) add8(__ldg(&H[(size_t)__ldg(&sl[i]) * 8 + q]));

    float4* o4 = (float4*)out;
    if (rmw) {
        float4 oa = o4[(size_t)node * 16 + 2 * q];
        float4 ob = o4[(size_t)node * 16 + 2 * q + 1];
        oa.x += acc[0]; oa.y += acc[1]; oa.z += acc[2]; oa.w += acc[3];
        ob.x += acc[4]; ob.y += acc[5]; ob.z += acc[6]; ob.w += acc[7];
        o4[(size_t)node * 16 + 2 * q] = oa;
        o4[(size_t)node * 16 + 2 * q + 1] = ob;
    } else {
        o4[(size_t)node * 16 + 2 * q]     = make_float4(acc[0], acc[1], acc[2], acc[3]);
        o4[(size_t)node * 16 + 2 * q + 1] = make_float4(acc[4], acc[5], acc[6], acc[7]);
    }
}

// Overflow edges (deg > CAP): add the missed W2[t]*x[src] + b2[t] to out[dst].
__global__ void ovf_kernel(const float* __restrict__ x,
                           const int* __restrict__ ntype,
                           const float* __restrict__ W2,
                           const float* __restrict__ b2,
                           float* __restrict__ out) {
    int n = g_ovf_cnt;
    if (n > 8192) n = 8192;
    int wid = (blockIdx.x * blockDim.x + threadIdx.x) >> 5;
    int lane = threadIdx.x & 31;
    int nwarps = (gridDim.x * blockDim.x) >> 5;
    for (int ei = wid; ei < n; ei += nwarps) {
        int2 sd = g_ovf[ei];
        int src = sd.x, dst = sd.y;
        int t = ntype[src];
        int c = lane * 2;
        float s0 = b2[t * 64 + c], s1 = b2[t * 64 + c + 1];
        for (int k = 0; k < 64; k++) {
            float xv = __ldg(&x[(size_t)src * 64 + k]);
            s0 += xv * __ldg(&W2[(size_t)t * 4096 + k * 64 + c]);
            s1 += xv * __ldg(&W2[(size_t)t * 4096 + k * 64 + c + 1]);
        }
        atomicAdd(&out[(size_t)dst * 64 + c], s0);
        atomicAdd(&out[(size_t)dst * 64 + c + 1], s1);
    }
}

// ---------------- launch ----------------
extern "C" void kernel_launch(void* const* d_in, const int* in_sizes, int n_in,
                              void* d_out, int out_size) {
    const float *x = nullptr, *ef = nullptr;
    const float *W[4] = {nullptr, nullptr, nullptr, nullptr};
    const float *B[4] = {nullptr, nullptr, nullptr, nullptr};
    const float *W5 = nullptr, *b5 = nullptr;
    const int *ntype = nullptr, *esrc = nullptr, *edst = nullptr, *etype = nullptr;
    int wI = 0, bI = 0, mI = 0;
    for (int i = 0; i < n_in; i++) {
        long s = in_sizes[i];
        const void* p = d_in[i];
        if (s == (long)Nn * 64)       x = (const float*)p;
        else if (s == (long)Mm * 16)  ef = (const float*)p;
        else if (s == Nn)             ntype = (const int*)p;
        else if (s == Mm) {
            if (mI == 0) esrc = (const int*)p;
            else if (mI == 1) edst = (const int*)p;
            else etype = (const int*)p;
            mI++;
        }
        else if (s == 2 * 64 * 64) { if (wI < 4) W[wI++] = (const float*)p; }
        else if (s == 2 * 64)      { if (bI < 4) B[bI++] = (const float*)p; }
        else if (s == 3 * 16 * 64) W5 = (const float*)p;
        else if (s == 3 * 64)      b5 = (const float*)p;
    }
    float* out = (float*)d_out;

    cudaStream_t s2;
    cudaEvent_t evFork, evH2, evScat, evH1A, evGB, evGA;
    bool forked =
        (cudaStreamCreateWithFlags(&s2, cudaStreamNonBlocking) == cudaSuccess) &&
        (cudaEventCreateWithFlags(&evFork, cudaEventDisableTiming) == cudaSuccess) &&
        (cudaEventCreateWithFlags(&evH2, cudaEventDisableTiming) == cudaSuccess) &&
        (cudaEventCreateWithFlags(&evScat, cudaEventDisableTiming) == cudaSuccess) &&
        (cudaEventCreateWithFlags(&evH1A, cudaEventDisableTiming) == cudaSuccess) &&
        (cudaEventCreateWithFlags(&evGB, cudaEventDisableTiming) == cudaSuccess) &&
        (cudaEventCreateWithFlags(&evGA, cudaEventDisableTiming) == cudaSuccess);

    const int h2_smem = 4096 * 4 + 128 * 4;   // 16.5 KB
    const int h1_smem = 6144 * 4 + 128 * 4;   // 24.5 KB
    const int cntA = SPLIT, cntB = Nn - SPLIT;

    if (forked) {
        // fork: h2_gemm (independent) on side stream
        cudaEventRecord(evFork, 0);
        cudaStreamWaitEvent(s2, evFork, 0);
        h2_gemm_kernel<<<296, 256, h2_smem, s2>>>(x, ntype, W[1], B[1]);
        cudaEventRecord(evH2, s2);

        // main: edge path
        zero_kernel<<<1024, 256>>>();
        edge_scatter_kernel<<<(Mm * 2 + 255) / 256, 256>>>(ef, esrc, edst, etype);
        cudaEventRecord(evScat, 0);

        // join both ways: main gets h2/xh; side gets slots/cur/aggE
        cudaStreamWaitEvent(0, evH2, 0);
        cudaStreamWaitEvent(s2, evScat, 0);

        // phase 1: h1(A, write) ‖ gatherH(B, write)
        h1_gemm_kernel<<<296, 256, h1_smem>>>(ntype, W[0], B[0], W5, b5, out,
                                              0, cntA, 0);
        gatherH_kernel<<<(cntB + 31) / 32, 256, 0, s2>>>(out, SPLIT, cntB, 0);
        cudaEventRecord(evH1A, 0);
        cudaEventRecord(evGB, s2);

        // phase 2: h1(B, rmw) ‖ gatherH(A, rmw)
        cudaStreamWaitEvent(0, evGB, 0);
        cudaStreamWaitEvent(s2, evH1A, 0);
        h1_gemm_kernel<<<296, 256, h1_smem>>>(ntype, W[0], B[0], W5, b5, out,
                                              SPLIT, cntB, 1);
        gatherH_kernel<<<(cntA + 31) / 32, 256, 0, s2>>>(out, 0, cntA, 1);
        cudaEventRecord(evGA, s2);
        cudaStreamWaitEvent(0, evGA, 0);

        ovf_kernel<<<8, 256>>>(x, ntype, W[1], B[1], out);
    } else {
        zero_kernel<<<1024, 256>>>();
        edge_scatter_kernel<<<(Mm * 2 + 255) / 256, 256>>>(ef, esrc, edst, etype);
        h2_gemm_kernel<<<296, 256, h2_smem>>>(x, ntype, W[1], B[1]);
        h1_gemm_kernel<<<296, 256, h1_smem>>>(ntype, W[0], B[0], W5, b5, out,
                                              0, Nn, 0);
        gatherH_kernel<<<(Nn + 31) / 32, 256>>>(out, 0, Nn, 1);
        ovf_kernel<<<8, 256>>>(x, ntype, W[1], B[1], out);
    }
}

// round 14
// speedup vs baseline: 1.1246x; 1.1246x over previous
#include <cuda_runtime.h>
#include <cuda_fp16.h>
#include <cstdint>

#define Nn 100000
#define Mm 800000
#define CAP 48

// ---------------- device scratch (no allocations allowed) ----------------
__device__ __half    g_h2h[(size_t)Nn * 64];    // h2 rows fp16, FRAGMENT-PERMUTED:
                                                //   word tq*8+nt = cols(8nt+2tq, 8nt+2tq+1)
__device__ __half    g_xh[(size_t)Nn * 64];     // x rows fp16 (identity col order)
__device__ uint32_t  g_aggEh[(size_t)Nn * 32];  // fp16 aggE rows; words 24..31 pad
__device__ int       g_cur[Nn];                 // packed: tot(10)|c1(10)|c2(10)
__device__ int       g_slots[(size_t)Nn * CAP]; // src node per bucket slot
__device__ int       g_ovf_cnt;
__device__ int2      g_ovf[8192];               // overflow: (src, dst)

__device__ __forceinline__ void red_add_h8(uint32_t* p, uint32_t a, uint32_t b,
                                           uint32_t c, uint32_t d) {
    asm volatile("red.global.add.noftz.v4.f16x2 [%0], {%1,%2,%3,%4};"
                 :: "l"(p), "r"(a), "r"(b), "r"(c), "r"(d) : "memory");
}

__device__ __forceinline__ void mma_f16(float c[4], uint32_t a0, uint32_t a1,
                                        uint32_t a2, uint32_t a3,
                                        uint32_t b0, uint32_t b1) {
    asm volatile(
        "mma.sync.aligned.m16n8k16.row.col.f32.f16.f16.f32 "
        "{%0,%1,%2,%3},{%4,%5,%6,%7},{%8,%9},{%0,%1,%2,%3};"
        : "+f"(c[0]), "+f"(c[1]), "+f"(c[2]), "+f"(c[3])
        : "r"(a0), "r"(a1), "r"(a2), "r"(a3), "r"(b0), "r"(b1));
}

__device__ __forceinline__ uint32_t pack_h2(float a, float b) {
    __half2 h = __floats2half2_rn(a, b);
    return *(uint32_t*)&h;
}

// ---------------- kernels ----------------

__global__ void zero_kernel() {
    int gid = blockIdx.x * blockDim.x + threadIdx.x;
    int stride = gridDim.x * blockDim.x;
    uint4 z = make_uint4(0u, 0u, 0u, 0u);
    uint4* a4 = (uint4*)g_aggEh;
    for (int i = gid; i < Nn * 8; i += stride) a4[i] = z;
    for (int i = gid; i < Nn; i += stride) g_cur[i] = 0;
    if (gid == 0) g_ovf_cnt = 0;
}

// 2 threads/edge: fp16x8 red into aggE row + packed cursor + bucket fill
__global__ void edge_scatter_kernel(const float* __restrict__ ef,
                                    const int* __restrict__ esrc,
                                    const int* __restrict__ edst,
                                    const int* __restrict__ etype) {
    int gid = blockIdx.x * blockDim.x + threadIdx.x;
    int e = gid >> 1, q = gid & 1;
    if (e >= Mm) return;
    int dst = edst[e];
    int t   = etype[e];
    const float4* ef4 = (const float4*)ef;
    float4 v0 = ef4[e * 4 + q * 2];
    float4 v1 = ef4[e * 4 + q * 2 + 1];
    uint32_t h0 = pack_h2(v0.x, v0.y), h1 = pack_h2(v0.z, v0.w);
    uint32_t h2 = pack_h2(v1.x, v1.y), h3 = pack_h2(v1.z, v1.w);
    red_add_h8(g_aggEh + (size_t)dst * 32 + t * 8 + q * 4, h0, h1, h2, h3);
    if (q == 0) {
        int inc = 1 + ((t == 1) ? (1 << 10) : 0) + ((t == 2) ? (1 << 20) : 0);
        int old = atomicAdd(&g_cur[dst], inc);
        int p = old & 1023;
        int src = esrc[e];
        if (p < CAP) {
            g_slots[(size_t)dst * CAP + p] = src;
        } else {
            int o = atomicAdd(&g_ovf_cnt, 1);
            if (o < 8192) g_ovf[o] = make_int2(src, dst);
        }
    }
}

// h2 GEMM (side stream): A = [x*(t==0) | x*(t==1)] k=128, fp32 x via float4.
// Writes h2h (fp16, FRAGMENT-PERMUTED) and x as fp16 (g_xh, identity order).
__global__ __launch_bounds__(256, 2)
void h2_gemm_kernel(const float* __restrict__ x,
                    const int* __restrict__ ntype,
                    const float* __restrict__ W2, const float* __restrict__ b2) {
    extern __shared__ uint32_t smu[];
    uint4* Wf = (uint4*)smu;                 // [8][4][32] uint4 = 16 KB
    float* bc = (float*)(smu + 4096);        // [128]

    const int tid = threadIdx.x;
    const int w = tid >> 5, lane = tid & 31;
    const int g = lane >> 2, tq = lane & 3;

    for (int idx = tid; idx < 1024; idx += 256) {
        int ln = idx & 31;
        int ntp = (idx >> 5) & 3;
        int kb = idx >> 7;                    // 0..7
        int tqf = ln & 3, gf = ln >> 2;
        int ty = kb >> 2, p = kb & 3;
        int col0 = (2 * ntp) * 8 + gf;
        int col1 = col0 + 8;
        auto wv2 = [&](int h, int outc) -> uint32_t {
            int ca = 16 * p + 4 * tqf + 2 * h;
            return pack_h2(W2[(size_t)ty * 4096 + ca * 64 + outc],
                           W2[(size_t)ty * 4096 + (ca + 1) * 64 + outc]);
        };
        uint4 wv;
        wv.x = wv2(0, col0); wv.y = wv2(1, col0);
        wv.z = wv2(0, col1); wv.w = wv2(1, col1);
        Wf[idx] = wv;
    }
    if (tid < 128) bc[tid] = b2[tid];
    __syncthreads();

    const int G = Nn >> 4;
    const int nwarps = gridDim.x << 3;
    __half2* h2p = (__half2*)g_h2h;
    uint32_t* xh32 = (uint32_t*)g_xh;
    const float4* xp4 = (const float4*)x;

    for (int grp = blockIdx.x * 8 + w; grp < G; grp += nwarps) {
        int base = grp << 4;
        uint32_t xw[2][8], msk[2];
        int tt[2];
        #pragma unroll
        for (int j = 0; j < 2; j++) {
            int node = base + g + 8 * j;
            tt[j] = __ldg(&ntype[node]);
            msk[j] = (tt[j] == 0) ? 0xFFFFFFFFu : 0u;
            #pragma unroll
            for (int m = 0; m < 4; m++) {
                float4 f = xp4[(size_t)node * 16 + 4 * m + tq];
                xw[j][2 * m]     = pack_h2(f.x, f.y);
                xw[j][2 * m + 1] = pack_h2(f.z, f.w);
            }
        }

        float acc[8][4];
        #pragma unroll
        for (int nt = 0; nt < 8; nt++)
            #pragma unroll
            for (int jj = 0; jj < 4; jj++) acc[nt][jj] = 0.f;

        #pragma unroll
        for (int kb = 0; kb < 8; kb++) {
            int p = kb & 3;
            uint32_t s0 = (kb < 4) ? msk[0] : ~msk[0];
            uint32_t s1 = (kb < 4) ? msk[1] : ~msk[1];
            uint32_t a0 = xw[0][2 * p] & s0;
            uint32_t a2 = xw[0][2 * p + 1] & s0;
            uint32_t a1 = xw[1][2 * p] & s1;
            uint32_t a3 = xw[1][2 * p + 1] & s1;
            #pragma unroll
            for (int ntp = 0; ntp < 4; ntp++) {
                uint4 bw = Wf[(kb * 4 + ntp) * 32 + lane];
                mma_f16(acc[2 * ntp], a0, a1, a2, a3, bw.x, bw.y);
                mma_f16(acc[2 * ntp + 1], a0, a1, a2, a3, bw.z, bw.w);
            }
        }

        #pragma unroll
        for (int j = 0; j < 2; j++) {
            int node = base + g + 8 * j;
            int t = tt[j];
            uint2* xdst = (uint2*)(xh32 + (size_t)node * 32);
            #pragma unroll
            for (int m = 0; m < 4; m++)
                xdst[(8 * m + 2 * tq) >> 1] = make_uint2(xw[j][2 * m], xw[j][2 * m + 1]);
            #pragma unroll
            for (int nt = 0; nt < 8; nt++) {
                int col0 = nt * 8 + 2 * tq;
                float v0 = acc[nt][2 * j + 0] + bc[t * 64 + col0];
                float v1 = acc[nt][2 * j + 1] + bc[t * 64 + col0 + 1];
                // FRAGMENT-PERMUTED store: word tq*8+nt
                h2p[(size_t)node * 32 + tq * 8 + nt] = __floats2half2_rn(v0, v1);
            }
        }
    }
}

// Fused h1 GEMM + h2 gather. A = [x*(t==0)(64) | x*(t==1)(64) | tail(64)],
// k=192, fp16 inputs via 4x LDG.128 per node. Gather: each warp owns its 16
// nodes entirely; per (thread, edge) 2x LDG.128 from fragment-permuted h2h,
// accumulated directly into the MMA accumulators. out written exactly once.
__global__ __launch_bounds__(256, 2)
void h1_fused_kernel(const int* __restrict__ ntype,
                     const float* __restrict__ W1, const float* __restrict__ b1,
                     const float* __restrict__ W5, const float* __restrict__ b5,
                     float* __restrict__ out) {
    extern __shared__ uint32_t smu[];
    uint4* Wf = (uint4*)smu;                 // [12][4][32] uint4 = 24 KB
    float* bc = (float*)(smu + 6144);        // [128]

    const int tid = threadIdx.x;
    const int w = tid >> 5, lane = tid & 31;
    const int g = lane >> 2, tq = lane & 3;

    for (int idx = tid; idx < 1536; idx += 256) {
        int ln = idx & 31;
        int ntp = (idx >> 5) & 3;
        int kb = idx >> 7;                    // 0..11
        int tqf = ln & 3, gf = ln >> 2;
        int col0 = (2 * ntp) * 8 + gf;
        int col1 = col0 + 8;
        auto val = [&](int h, int elem, int outc) -> float {
            if (kb < 8) {
                int ty = kb >> 2, p = kb & 3;
                int wd = 16 * (p >> 1) + 4 * tqf + 2 * (p & 1) + h;
                int hh = 2 * wd + elem;
                return W1[(size_t)ty * 4096 + hh * 64 + outc];
            } else {
                int p = kb - 8;
                int wd = 16 * (p >> 1) + 4 * tqf + 2 * (p & 1) + h;
                if (wd < 24) {
                    int t = wd >> 3, colf = 2 * (wd & 7) + elem;
                    return W5[(size_t)(t * 16 + colf) * 64 + outc];
                }
                if (wd == 24) return b5[elem * 64 + outc];
                if (wd == 25) return (elem == 0) ? b5[128 + outc] : 0.f;
                return 0.f;
            }
        };
        uint4 wv;
        wv.x = pack_h2(val(0, 0, col0), val(0, 1, col0));
        wv.y = pack_h2(val(1, 0, col0), val(1, 1, col0));
        wv.z = pack_h2(val(0, 0, col1), val(0, 1, col1));
        wv.w = pack_h2(val(1, 0, col1), val(1, 1, col1));
        Wf[idx] = wv;
    }
    if (tid < 128) bc[tid] = b1[tid];
    __syncthreads();

    const int G = Nn >> 4;
    const int nwarps = gridDim.x << 3;
    float2* outp = (float2*)out;
    const uint4* xh4 = (const uint4*)g_xh;
    const uint4* ag4 = (const uint4*)g_aggEh;
    const uint4* H4 = (const uint4*)g_h2h;   // 8 uint4 per row

    for (int grp = blockIdx.x * 8 + w; grp < G; grp += nwarps) {
        int base = grp << 4;
        uint4 xu[2][2], tu[2][2];
        uint32_t msk[2];
        int tt[2], deg[2], cv[2];
        #pragma unroll
        for (int j = 0; j < 2; j++) {
            int node = base + g + 8 * j;
            tt[j] = __ldg(&ntype[node]);
            msk[j] = (tt[j] == 0) ? 0xFFFFFFFFu : 0u;
            xu[j][0] = __ldg(&xh4[(size_t)node * 8 + tq]);
            xu[j][1] = __ldg(&xh4[(size_t)node * 8 + tq + 4]);
            tu[j][0] = __ldg(&ag4[(size_t)node * 8 + tq]);
            tu[j][1] = __ldg(&ag4[(size_t)node * 8 + tq + 4]);
            cv[j] = __ldg(&g_cur[node]);
            int d = cv[j] & 1023;
            deg[j] = (d > CAP) ? CAP : d;
        }
        #pragma unroll
        for (int j = 0; j < 2; j++) {
            if (tq == 2) {
                int tot = cv[j] & 1023, c1i = (cv[j] >> 10) & 1023, c2i = cv[j] >> 20;
                tu[j][1].x = pack_h2((float)(tot - c1i - c2i), (float)c1i);
                tu[j][1].y = pack_h2((float)c2i, 0.f);
            }
        }

        float acc[8][4];
        #pragma unroll
        for (int nt = 0; nt < 8; nt++)
            #pragma unroll
            for (int jj = 0; jj < 4; jj++) acc[nt][jj] = 0.f;

        // ---- fused gather: acc[nt][2j+e] += sum over edges of h2[src] ----
        #pragma unroll
        for (int j = 0; j < 2; j++) {
            int node = base + g + 8 * j;
            const int* sl = &g_slots[(size_t)node * CAP];
            auto addfrag = [&](uint4 va, uint4 vb) {
                float2 f;
                f = __half22float2(*(__half2*)&va.x); acc[0][2*j] += f.x; acc[0][2*j+1] += f.y;
                f = __half22float2(*(__half2*)&va.y); acc[1][2*j] += f.x; acc[1][2*j+1] += f.y;
                f = __half22float2(*(__half2*)&va.z); acc[2][2*j] += f.x; acc[2][2*j+1] += f.y;
                f = __half22float2(*(__half2*)&va.w); acc[3][2*j] += f.x; acc[3][2*j+1] += f.y;
                f = __half22float2(*(__half2*)&vb.x); acc[4][2*j] += f.x; acc[4][2*j+1] += f.y;
                f = __half22float2(*(__half2*)&vb.y); acc[5][2*j] += f.x; acc[5][2*j+1] += f.y;
                f = __half22float2(*(__half2*)&vb.z); acc[6][2*j] += f.x; acc[6][2*j+1] += f.y;
                f = __half22float2(*(__half2*)&vb.w); acc[7][2*j] += f.x; acc[7][2*j+1] += f.y;
            };
            int d = deg[j];
            int i = 0;
            for (; i + 2 <= d; i += 2) {
                int s0 = __ldg(&sl[i]);
                int s1 = __ldg(&sl[i + 1]);
                uint4 a0 = __ldg(&H4[(size_t)s0 * 8 + tq * 2]);
                uint4 b0 = __ldg(&H4[(size_t)s0 * 8 + tq * 2 + 1]);
                uint4 a1 = __ldg(&H4[(size_t)s1 * 8 + tq * 2]);
                uint4 b1v = __ldg(&H4[(size_t)s1 * 8 + tq * 2 + 1]);
                addfrag(a0, b0);
                addfrag(a1, b1v);
            }
            if (i < d) {
                int s0 = __ldg(&sl[i]);
                uint4 a0 = __ldg(&H4[(size_t)s0 * 8 + tq * 2]);
                uint4 b0 = __ldg(&H4[(size_t)s0 * 8 + tq * 2 + 1]);
                addfrag(a0, b0);
            }
        }

        // ---- MMA on top of gathered partial sums ----
        auto slot = [&](uint4 uq[2], int p, int h) -> uint32_t {
            uint4 uu = uq[p >> 1];
            return (p & 1) ? (h ? uu.w : uu.z) : (h ? uu.y : uu.x);
        };

        #pragma unroll
        for (int kb = 0; kb < 12; kb++) {
            uint32_t a0, a1, a2, a3;
            if (kb < 8) {
                int p = kb & 3;
                uint32_t s0 = (kb < 4) ? msk[0] : ~msk[0];
                uint32_t s1 = (kb < 4) ? msk[1] : ~msk[1];
                a0 = slot(xu[0], p, 0) & s0;
                a2 = slot(xu[0], p, 1) & s0;
                a1 = slot(xu[1], p, 0) & s1;
                a3 = slot(xu[1], p, 1) & s1;
            } else {
                int p = kb - 8;
                a0 = slot(tu[0], p, 0); a2 = slot(tu[0], p, 1);
                a1 = slot(tu[1], p, 0); a3 = slot(tu[1], p, 1);
            }
            #pragma unroll
            for (int ntp = 0; ntp < 4; ntp++) {
                uint4 bw = Wf[(kb * 4 + ntp) * 32 + lane];
                mma_f16(acc[2 * ntp], a0, a1, a2, a3, bw.x, bw.y);
                mma_f16(acc[2 * ntp + 1], a0, a1, a2, a3, bw.z, bw.w);
            }
        }

        #pragma unroll
        for (int j = 0; j < 2; j++) {
            int node = base + g + 8 * j;
            int t = tt[j];
            #pragma unroll
            for (int nt = 0; nt < 8; nt++) {
                int col0 = nt * 8 + 2 * tq;
                float v0 = acc[nt][2 * j + 0] + bc[t * 64 + col0];
                float v1 = acc[nt][2 * j + 1] + bc[t * 64 + col0 + 1];
                outp[(size_t)node * 32 + nt * 4 + tq] = make_float2(v0, v1);
            }
        }
    }
}

// Overflow edges (deg > CAP): add the missed W2[t]*x[src] + b2[t] to out[dst].
__global__ void ovf_kernel(const float* __restrict__ x,
                           const int* __restrict__ ntype,
                           const float* __restrict__ W2,
                           const float* __restrict__ b2,
                           float* __restrict__ out) {
    int n = g_ovf_cnt;
    if (n > 8192) n = 8192;
    int wid = (blockIdx.x * blockDim.x + threadIdx.x) >> 5;
    int lane = threadIdx.x & 31;
    int nwarps = (gridDim.x * blockDim.x) >> 5;
    for (int ei = wid; ei < n; ei += nwarps) {
        int2 sd = g_ovf[ei];
        int src = sd.x, dst = sd.y;
        int t = ntype[src];
        int c = lane * 2;
        float s0 = b2[t * 64 + c], s1 = b2[t * 64 + c + 1];
        for (int k = 0; k < 64; k++) {
            float xv = __ldg(&x[(size_t)src * 64 + k]);
            s0 += xv * __ldg(&W2[(size_t)t * 4096 + k * 64 + c]);
            s1 += xv * __ldg(&W2[(size_t)t * 4096 + k * 64 + c + 1]);
        }
        atomicAdd(&out[(size_t)dst * 64 + c], s0);
        atomicAdd(&out[(size_t)dst * 64 + c + 1], s1);
    }
}

// ---------------- launch ----------------
extern "C" void kernel_launch(void* const* d_in, const int* in_sizes, int n_in,
                              void* d_out, int out_size) {
    const float *x = nullptr, *ef = nullptr;
    const float *W[4] = {nullptr, nullptr, nullptr, nullptr};
    const float *B[4] = {nullptr, nullptr, nullptr, nullptr};
    const float *W5 = nullptr, *b5 = nullptr;
    const int *ntype = nullptr, *esrc = nullptr, *edst = nullptr, *etype = nullptr;
    int wI = 0, bI = 0, mI = 0;
    for (int i = 0; i < n_in; i++) {
        long s = in_sizes[i];
        const void* p = d_in[i];
        if (s == (long)Nn * 64)       x = (const float*)p;
        else if (s == (long)Mm * 16)  ef = (const float*)p;
        else if (s == Nn)             ntype = (const int*)p;
        else if (s == Mm) {
            if (mI == 0) esrc = (const int*)p;
            else if (mI == 1) edst = (const int*)p;
            else etype = (const int*)p;
            mI++;
        }
        else if (s == 2 * 64 * 64) { if (wI < 4) W[wI++] = (const float*)p; }
        else if (s == 2 * 64)      { if (bI < 4) B[bI++] = (const float*)p; }
        else if (s == 3 * 16 * 64) W5 = (const float*)p;
        else if (s == 3 * 64)      b5 = (const float*)p;
    }
    float* out = (float*)d_out;

    cudaStream_t s2;
    cudaEvent_t evFork, evJoin;
    bool forked = (cudaStreamCreateWithFlags(&s2, cudaStreamNonBlocking) == cudaSuccess)
               && (cudaEventCreateWithFlags(&evFork, cudaEventDisableTiming) == cudaSuccess)
               && (cudaEventCreateWithFlags(&evJoin, cudaEventDisableTiming) == cudaSuccess);

    const int h2_smem = 4096 * 4 + 128 * 4;   // 16.5 KB
    const int h1_smem = 6144 * 4 + 128 * 4;   // 24.5 KB

    if (forked) {
        cudaEventRecord(evFork, 0);
        cudaStreamWaitEvent(s2, evFork, 0);
        h2_gemm_kernel<<<296, 256, h2_smem, s2>>>(x, ntype, W[1], B[1]);
        cudaEventRecord(evJoin, s2);
    } else {
        h2_gemm_kernel<<<296, 256, h2_smem>>>(x, ntype, W[1], B[1]);
    }

    zero_kernel<<<1024, 256>>>();
    edge_scatter_kernel<<<(Mm * 2 + 255) / 256, 256>>>(ef, esrc, edst, etype);
    if (forked) cudaStreamWaitEvent(0, evJoin, 0);
    h1_fused_kernel<<<296, 256, h1_smem>>>(ntype, W[0], B[0], W5, b5, out);
    ovf_kernel<<<8, 256>>>(x, ntype, W[1], B[1], out);
}

// round 15
// speedup vs baseline: 1.1259x; 1.0011x over previous
#include <cuda_runtime.h>
#include <cuda_fp16.h>
#include <cstdint>

#define Nn 100000
#define Mm 800000
#define CAP 48

// ---------------- device scratch (no allocations allowed) ----------------
__device__ __half    g_h2h[(size_t)Nn * 64];    // h2 rows fp16 (identity col order)
__device__ __half    g_xh[(size_t)Nn * 64];     // x rows fp16 (identity col order)
__device__ uint32_t  g_aggEh[(size_t)Nn * 32];  // fp16 aggE rows; words 24..31 pad
__device__ int       g_cur[Nn];                 // packed: tot(10)|c1(10)|c2(10)
__device__ int       g_slots[(size_t)Nn * CAP]; // src node per bucket slot
__device__ int       g_ovf_cnt;
__device__ int2      g_ovf[8192];               // overflow: (src, dst)
__device__ uint4     g_Wf1[1536];               // h1 B fragments (W1|W5|b5)
__device__ uint4     g_Wf2[1024];               // h2 B fragments (W2)

__device__ __forceinline__ void red_add_h8(uint32_t* p, uint32_t a, uint32_t b,
                                           uint32_t c, uint32_t d) {
    asm volatile("red.global.add.noftz.v4.f16x2 [%0], {%1,%2,%3,%4};"
                 :: "l"(p), "r"(a), "r"(b), "r"(c), "r"(d) : "memory");
}

__device__ __forceinline__ void mma_f16(float c[4], uint32_t a0, uint32_t a1,
                                        uint32_t a2, uint32_t a3,
                                        uint32_t b0, uint32_t b1) {
    asm volatile(
        "mma.sync.aligned.m16n8k16.row.col.f32.f16.f16.f32 "
        "{%0,%1,%2,%3},{%4,%5,%6,%7},{%8,%9},{%0,%1,%2,%3};"
        : "+f"(c[0]), "+f"(c[1]), "+f"(c[2]), "+f"(c[3])
        : "r"(a0), "r"(a1), "r"(a2), "r"(a3), "r"(b0), "r"(b1));
}

__device__ __forceinline__ uint32_t pack_h2(float a, float b) {
    __half2 h = __floats2half2_rn(a, b);
    return *(uint32_t*)&h;
}

// ---------------- kernels ----------------

// Precompute B fragments for both GEMMs (fragment slot mapping:
// slot p: word(p,h) = 16*(p>>1) + 4*tqf + 2*(p&1) + h; x col = 2*wd+elem).
__global__ void prep_kernel(const float* __restrict__ W1,
                            const float* __restrict__ W2,
                            const float* __restrict__ W5,
                            const float* __restrict__ b5) {
    int gid = blockIdx.x * blockDim.x + threadIdx.x;
    int stride = gridDim.x * blockDim.x;
    for (int idx = gid; idx < 1536; idx += stride) {
        int ln = idx & 31;
        int ntp = (idx >> 5) & 3;
        int kb = idx >> 7;                    // 0..11
        int tqf = ln & 3, gf = ln >> 2;
        int col0 = (2 * ntp) * 8 + gf;
        int col1 = col0 + 8;
        auto val = [&](int h, int elem, int outc) -> float {
            if (kb < 8) {
                int ty = kb >> 2, p = kb & 3;
                int wd = 16 * (p >> 1) + 4 * tqf + 2 * (p & 1) + h;
                int hh = 2 * wd + elem;
                return W1[(size_t)ty * 4096 + hh * 64 + outc];
            } else {
                int p = kb - 8;
                int wd = 16 * (p >> 1) + 4 * tqf + 2 * (p & 1) + h;
                if (wd < 24) {
                    int t = wd >> 3, colf = 2 * (wd & 7) + elem;
                    return W5[(size_t)(t * 16 + colf) * 64 + outc];
                }
                if (wd == 24) return b5[elem * 64 + outc];
                if (wd == 25) return (elem == 0) ? b5[128 + outc] : 0.f;
                return 0.f;
            }
        };
        uint4 wv;
        wv.x = pack_h2(val(0, 0, col0), val(0, 1, col0));
        wv.y = pack_h2(val(1, 0, col0), val(1, 1, col0));
        wv.z = pack_h2(val(0, 0, col1), val(0, 1, col1));
        wv.w = pack_h2(val(1, 0, col1), val(1, 1, col1));
        g_Wf1[idx] = wv;
    }
    for (int idx = gid; idx < 1024; idx += stride) {
        int ln = idx & 31;
        int ntp = (idx >> 5) & 3;
        int kb = idx >> 7;                    // 0..7
        int tqf = ln & 3, gf = ln >> 2;
        int col0 = (2 * ntp) * 8 + gf;
        int col1 = col0 + 8;
        auto val2 = [&](int h, int elem, int outc) -> float {
            int ty = kb >> 2, p = kb & 3;
            int wd = 16 * (p >> 1) + 4 * tqf + 2 * (p & 1) + h;
            int hh = 2 * wd + elem;
            return W2[(size_t)ty * 4096 + hh * 64 + outc];
        };
        uint4 wv;
        wv.x = pack_h2(val2(0, 0, col0), val2(0, 1, col0));
        wv.y = pack_h2(val2(1, 0, col0), val2(1, 1, col0));
        wv.z = pack_h2(val2(0, 0, col1), val2(0, 1, col1));
        wv.w = pack_h2(val2(1, 0, col1), val2(1, 1, col1));
        g_Wf2[idx] = wv;
    }
}

// Convert x -> fp16 (identity word order)
__global__ void conv_kernel(const float* __restrict__ x) {
    int gid = blockIdx.x * blockDim.x + threadIdx.x;
    int stride = gridDim.x * blockDim.x;
    const float4* x4 = (const float4*)x;
    uint2* xo = (uint2*)g_xh;
    for (int i = gid; i < Nn * 16; i += stride) {
        float4 f = x4[i];
        xo[i] = make_uint2(pack_h2(f.x, f.y), pack_h2(f.z, f.w));
    }
}

__global__ void zero_kernel() {
    int gid = blockIdx.x * blockDim.x + threadIdx.x;
    int stride = gridDim.x * blockDim.x;
    uint4 z = make_uint4(0u, 0u, 0u, 0u);
    uint4* a4 = (uint4*)g_aggEh;
    for (int i = gid; i < Nn * 8; i += stride) a4[i] = z;
    for (int i = gid; i < Nn; i += stride) g_cur[i] = 0;
    if (gid == 0) g_ovf_cnt = 0;
}

// 2 threads/edge: fp16x8 red into aggE row + packed cursor + bucket fill
__global__ void edge_scatter_kernel(const float* __restrict__ ef,
                                    const int* __restrict__ esrc,
                                    const int* __restrict__ edst,
                                    const int* __restrict__ etype) {
    int gid = blockIdx.x * blockDim.x + threadIdx.x;
    int e = gid >> 1, q = gid & 1;
    if (e >= Mm) return;
    int dst = edst[e];
    int t   = etype[e];
    const float4* ef4 = (const float4*)ef;
    float4 v0 = ef4[e * 4 + q * 2];
    float4 v1 = ef4[e * 4 + q * 2 + 1];
    uint32_t h0 = pack_h2(v0.x, v0.y), h1 = pack_h2(v0.z, v0.w);
    uint32_t h2 = pack_h2(v1.x, v1.y), h3 = pack_h2(v1.z, v1.w);
    red_add_h8(g_aggEh + (size_t)dst * 32 + t * 8 + q * 4, h0, h1, h2, h3);
    if (q == 0) {
        int inc = 1 + ((t == 1) ? (1 << 10) : 0) + ((t == 2) ? (1 << 20) : 0);
        int old = atomicAdd(&g_cur[dst], inc);
        int p = old & 1023;
        int src = esrc[e];
        if (p < CAP) {
            g_slots[(size_t)dst * CAP + p] = src;
        } else {
            int o = atomicAdd(&g_ovf_cnt, 1);
            if (o < 8192) g_ovf[o] = make_int2(src, dst);
        }
    }
}

// h2 GEMM: A = [x*(t==0) | x*(t==1)] k=128, fp16 x via 2x LDG.128/node.
// B from g_Wf2 (copy to smem). Writes h2h (fp16, identity order).
__global__ __launch_bounds__(256, 2)
void h2_gemm_kernel(const int* __restrict__ ntype, const float* __restrict__ b2) {
    extern __shared__ uint32_t smu[];
    uint4* Wf = (uint4*)smu;                 // 1024 uint4 = 16 KB
    float* bc = (float*)(smu + 4096);        // [128]

    const int tid = threadIdx.x;
    const int w = tid >> 5, lane = tid & 31;
    const int g = lane >> 2, tq = lane & 3;

    for (int idx = tid; idx < 1024; idx += 256) Wf[idx] = g_Wf2[idx];
    if (tid < 128) bc[tid] = b2[tid];
    __syncthreads();

    const int G = Nn >> 4;
    const int nwarps = gridDim.x << 3;
    __half2* h2p = (__half2*)g_h2h;
    const uint4* xh4 = (const uint4*)g_xh;

    for (int grp = blockIdx.x * 8 + w; grp < G; grp += nwarps) {
        int base = grp << 4;
        uint4 xu[2][2];
        uint32_t msk[2];
        int tt[2];
        #pragma unroll
        for (int j = 0; j < 2; j++) {
            int node = base + g + 8 * j;
            tt[j] = __ldg(&ntype[node]);
            msk[j] = (tt[j] == 0) ? 0xFFFFFFFFu : 0u;
            xu[j][0] = __ldg(&xh4[(size_t)node * 8 + tq]);
            xu[j][1] = __ldg(&xh4[(size_t)node * 8 + tq + 4]);
        }

        float acc[8][4];
        #pragma unroll
        for (int nt = 0; nt < 8; nt++)
            #pragma unroll
            for (int jj = 0; jj < 4; jj++) acc[nt][jj] = 0.f;

        auto slot = [&](uint4 uq[2], int p, int h) -> uint32_t {
            uint4 uu = uq[p >> 1];
            return (p & 1) ? (h ? uu.w : uu.z) : (h ? uu.y : uu.x);
        };

        #pragma unroll
        for (int kb = 0; kb < 8; kb++) {
            int p = kb & 3;
            uint32_t s0 = (kb < 4) ? msk[0] : ~msk[0];
            uint32_t s1 = (kb < 4) ? msk[1] : ~msk[1];
            uint32_t a0 = slot(xu[0], p, 0) & s0;
            uint32_t a2 = slot(xu[0], p, 1) & s0;
            uint32_t a1 = slot(xu[1], p, 0) & s1;
            uint32_t a3 = slot(xu[1], p, 1) & s1;
            #pragma unroll
            for (int ntp = 0; ntp < 4; ntp++) {
                uint4 bw = Wf[(kb * 4 + ntp) * 32 + lane];
                mma_f16(acc[2 * ntp], a0, a1, a2, a3, bw.x, bw.y);
                mma_f16(acc[2 * ntp + 1], a0, a1, a2, a3, bw.z, bw.w);
            }
        }

        #pragma unroll
        for (int j = 0; j < 2; j++) {
            int node = base + g + 8 * j;
            int t = tt[j];
            #pragma unroll
            for (int nt = 0; nt < 8; nt++) {
                int col0 = nt * 8 + 2 * tq;
                float v0 = acc[nt][2 * j + 0] + bc[t * 64 + col0];
                float v1 = acc[nt][2 * j + 1] + bc[t * 64 + col0 + 1];
                h2p[(size_t)node * 32 + nt * 4 + tq] = __floats2half2_rn(v0, v1);
            }
        }
    }
}

// h1 GEMM: A = [x*(t==0)(64) | x*(t==1)(64) | tail(64)], k=192, fp16 inputs
// via 4x LDG.128/node. B from g_Wf1. out[node] = acc + b1[t], FULL write.
__global__ __launch_bounds__(256, 2)
void h1_gemm_kernel(const int* __restrict__ ntype, const float* __restrict__ b1,
                    float* __restrict__ out) {
    extern __shared__ uint32_t smu[];
    uint4* Wf = (uint4*)smu;                 // 1536 uint4 = 24 KB
    float* bc = (float*)(smu + 6144);        // [128]

    const int tid = threadIdx.x;
    const int w = tid >> 5, lane = tid & 31;
    const int g = lane >> 2, tq = lane & 3;

    for (int idx = tid; idx < 1536; idx += 256) Wf[idx] = g_Wf1[idx];
    if (tid < 128) bc[tid] = b1[tid];
    __syncthreads();

    const int G = Nn >> 4;
    const int nwarps = gridDim.x << 3;
    float2* outp = (float2*)out;
    const uint4* xh4 = (const uint4*)g_xh;
    const uint4* ag4 = (const uint4*)g_aggEh;

    for (int grp = blockIdx.x * 8 + w; grp < G; grp += nwarps) {
        int base = grp << 4;
        uint4 xu[2][2], tu[2][2];
        uint32_t msk[2];
        int tt[2];
        #pragma unroll
        for (int j = 0; j < 2; j++) {
            int node = base + g + 8 * j;
            tt[j] = __ldg(&ntype[node]);
            msk[j] = (tt[j] == 0) ? 0xFFFFFFFFu : 0u;
            xu[j][0] = __ldg(&xh4[(size_t)node * 8 + tq]);
            xu[j][1] = __ldg(&xh4[(size_t)node * 8 + tq + 4]);
            tu[j][0] = __ldg(&ag4[(size_t)node * 8 + tq]);
            tu[j][1] = __ldg(&ag4[(size_t)node * 8 + tq + 4]);
            int cv = __ldg(&g_cur[node]);
            if (tq == 2) {
                int tot = cv & 1023, c1i = (cv >> 10) & 1023, c2i = cv >> 20;
                tu[j][1].x = pack_h2((float)(tot - c1i - c2i), (float)c1i);
                tu[j][1].y = pack_h2((float)c2i, 0.f);
            }
        }

        float acc[8][4];
        #pragma unroll
        for (int nt = 0; nt < 8; nt++)
            #pragma unroll
            for (int jj = 0; jj < 4; jj++) acc[nt][jj] = 0.f;

        auto slot = [&](uint4 uq[2], int p, int h) -> uint32_t {
            uint4 uu = uq[p >> 1];
            return (p & 1) ? (h ? uu.w : uu.z) : (h ? uu.y : uu.x);
        };

        #pragma unroll
        for (int kb = 0; kb < 12; kb++) {
            uint32_t a0, a1, a2, a3;
            if (kb < 8) {
                int p = kb & 3;
                uint32_t s0 = (kb < 4) ? msk[0] : ~msk[0];
                uint32_t s1 = (kb < 4) ? msk[1] : ~msk[1];
                a0 = slot(xu[0], p, 0) & s0;
                a2 = slot(xu[0], p, 1) & s0;
                a1 = slot(xu[1], p, 0) & s1;
                a3 = slot(xu[1], p, 1) & s1;
            } else {
                int p = kb - 8;
                a0 = slot(tu[0], p, 0); a2 = slot(tu[0], p, 1);
                a1 = slot(tu[1], p, 0); a3 = slot(tu[1], p, 1);
            }
            #pragma unroll
            for (int ntp = 0; ntp < 4; ntp++) {
                uint4 bw = Wf[(kb * 4 + ntp) * 32 + lane];
                mma_f16(acc[2 * ntp], a0, a1, a2, a3, bw.x, bw.y);
                mma_f16(acc[2 * ntp + 1], a0, a1, a2, a3, bw.z, bw.w);
            }
        }

        #pragma unroll
        for (int j = 0; j < 2; j++) {
            int node = base + g + 8 * j;
            int t = tt[j];
            #pragma unroll
            for (int nt = 0; nt < 8; nt++) {
                int col0 = nt * 8 + 2 * tq;
                float v0 = acc[nt][2 * j + 0] + bc[t * 64 + col0];
                float v1 = acc[nt][2 * j + 1] + bc[t * 64 + col0 + 1];
                outp[(size_t)node * 32 + nt * 4 + tq] = make_float2(v0, v1);
            }
        }
    }
}

// Bucket gather: out[dst] += sum h2h[src]; 8 lanes/node; slots via uint4.
__global__ __launch_bounds__(256)
void gatherH_kernel(float* __restrict__ out) {
    int tid = threadIdx.x;
    int node = blockIdx.x * 32 + (tid >> 3);
    int q = tid & 7;
    if (node >= Nn) return;
    int deg = g_cur[node] & 1023;
    if (deg > CAP) deg = CAP;
    if (deg == 0) return;

    const uint4* H = (const uint4*)g_h2h;
    const int* sl = &g_slots[(size_t)node * CAP];
    const uint4* sl4 = (const uint4*)sl;
    float acc[8];
    #pragma unroll
    for (int u = 0; u < 8; u++) acc[u] = 0.f;

    auto add8 = [&](uint4 hv) {
        float2 f0 = __half22float2(*(__half2*)&hv.x);
        float2 f1 = __half22float2(*(__half2*)&hv.y);
        float2 f2 = __half22float2(*(__half2*)&hv.z);
        float2 f3 = __half22float2(*(__half2*)&hv.w);
        acc[0] += f0.x; acc[1] += f0.y; acc[2] += f1.x; acc[3] += f1.y;
        acc[4] += f2.x; acc[5] += f2.y; acc[6] += f3.x; acc[7] += f3.y;
    };

    int i = 0;
    for (; i + 8 <= deg; i += 8) {
        uint4 sa = __ldg(&sl4[i >> 2]);
        uint4 sb = __ldg(&sl4[(i >> 2) + 1]);
        uint4 v0 = __ldg(&H[(size_t)sa.x * 8 + q]);
        uint4 v1 = __ldg(&H[(size_t)sa.y * 8 + q]);
        uint4 v2 = __ldg(&H[(size_t)sa.z * 8 + q]);
        uint4 v3 = __ldg(&H[(size_t)sa.w * 8 + q]);
        uint4 v4 = __ldg(&H[(size_t)sb.x * 8 + q]);
        uint4 v5 = __ldg(&H[(size_t)sb.y * 8 + q]);
        uint4 v6 = __ldg(&H[(size_t)sb.z * 8 + q]);
        uint4 v7 = __ldg(&H[(size_t)sb.w * 8 + q]);
        add8(v0); add8(v1); add8(v2); add8(v3);
        add8(v4); add8(v5); add8(v6); add8(v7);
    }
    for (; i + 4 <= deg; i += 4) {
        uint4 sa = __ldg(&sl4[i >> 2]);
        uint4 v0 = __ldg(&H[(size_t)sa.x * 8 + q]);
        uint4 v1 = __ldg(&H[(size_t)sa.y * 8 + q]);
        uint4 v2 = __ldg(&H[(size_t)sa.z * 8 + q]);
        uint4 v3 = __ldg(&H[(size_t)sa.w * 8 + q]);
        add8(v0); add8(v1); add8(v2); add8(v3);
    }
    for (; i < deg; i++) add8(__ldg(&H[(size_t)__ldg(&sl[i]) * 8 + q]));

    float4* o4 = (float4*)out;
    float4 oa = o4[(size_t)node * 16 + 2 * q];
    float4 ob = o4[(size_t)node * 16 + 2 * q + 1];
    oa.x += acc[0]; oa.y += acc[1]; oa.z += acc[2]; oa.w += acc[3];
    ob.x += acc[4]; ob.y += acc[5]; ob.z += acc[6]; ob.w += acc[7];
    o4[(size_t)node * 16 + 2 * q] = oa;
    o4[(size_t)node * 16 + 2 * q + 1] = ob;
}

// Overflow edges (deg > CAP): add the missed W2[t]*x[src] + b2[t] to out[dst].
__global__ void ovf_kernel(const float* __restrict__ x,
                           const int* __restrict__ ntype,
                           const float* __restrict__ W2,
                           const float* __restrict__ b2,
                           float* __restrict__ out) {
    int n = g_ovf_cnt;
    if (n > 8192) n = 8192;
    int wid = (blockIdx.x * blockDim.x + threadIdx.x) >> 5;
    int lane = threadIdx.x & 31;
    int nwarps = (gridDim.x * blockDim.x) >> 5;
    for (int ei = wid; ei < n; ei += nwarps) {
        int2 sd = g_ovf[ei];
        int src = sd.x, dst = sd.y;
        int t = ntype[src];
        int c = lane * 2;
        float s0 = b2[t * 64 + c], s1 = b2[t * 64 + c + 1];
        for (int k = 0; k < 64; k++) {
            float xv = __ldg(&x[(size_t)src * 64 + k]);
            s0 += xv * __ldg(&W2[(size_t)t * 4096 + k * 64 + c]);
            s1 += xv * __ldg(&W2[(size_t)t * 4096 + k * 64 + c + 1]);
        }
        atomicAdd(&out[(size_t)dst * 64 + c], s0);
        atomicAdd(&out[(size_t)dst * 64 + c + 1], s1);
    }
}

// ---------------- launch ----------------
extern "C" void kernel_launch(void* const* d_in, const int* in_sizes, int n_in,
                              void* d_out, int out_size) {
    const float *x = nullptr, *ef = nullptr;
    const float *W[4] = {nullptr, nullptr, nullptr, nullptr};
    const float *B[4] = {nullptr, nullptr, nullptr, nullptr};
    const float *W5 = nullptr, *b5 = nullptr;
    const int *ntype = nullptr, *esrc = nullptr, *edst = nullptr, *etype = nullptr;
    int wI = 0, bI = 0, mI = 0;
    for (int i = 0; i < n_in; i++) {
        long s = in_sizes[i];
        const void* p = d_in[i];
        if (s == (long)Nn * 64)       x = (const float*)p;
        else if (s == (long)Mm * 16)  ef = (const float*)p;
        else if (s == Nn)             ntype = (const int*)p;
        else if (s == Mm) {
            if (mI == 0) esrc = (const int*)p;
            else if (mI == 1) edst = (const int*)p;
            else etype = (const int*)p;
            mI++;
        }
        else if (s == 2 * 64 * 64) { if (wI < 4) W[wI++] = (const float*)p; }
        else if (s == 2 * 64)      { if (bI < 4) B[bI++] = (const float*)p; }
        else if (s == 3 * 16 * 64) W5 = (const float*)p;
        else if (s == 3 * 64)      b5 = (const float*)p;
    }
    float* out = (float*)d_out;

    cudaStream_t s2;
    cudaEvent_t evFork, evJoin;
    bool forked = (cudaStreamCreateWithFlags(&s2, cudaStreamNonBlocking) == cudaSuccess)
               && (cudaEventCreateWithFlags(&evFork, cudaEventDisableTiming) == cudaSuccess)
               && (cudaEventCreateWithFlags(&evJoin, cudaEventDisableTiming) == cudaSuccess);

    const int h2_smem = 4096 * 4 + 128 * 4;   // 16.5 KB
    const int h1_smem = 6144 * 4 + 128 * 4;   // 24.5 KB

    if (forked) {
        cudaEventRecord(evFork, 0);
        cudaStreamWaitEvent(s2, evFork, 0);
        prep_kernel<<<10, 256, 0, s2>>>(W[0], W[1], W5, b5);
        conv_kernel<<<512, 256, 0, s2>>>(x);
        h2_gemm_kernel<<<296, 256, h2_smem, s2>>>(ntype, B[1]);
        cudaEventRecord(evJoin, s2);

        zero_kernel<<<1024, 256>>>();
        edge_scatter_kernel<<<(Mm * 2 + 255) / 256, 256>>>(ef, esrc, edst, etype);
        cudaStreamWaitEvent(0, evJoin, 0);
        h1_gemm_kernel<<<296, 256, h1_smem>>>(ntype, B[0], out);
        gatherH_kernel<<<(Nn + 31) / 32, 256>>>(out);
        ovf_kernel<<<8, 256>>>(x, ntype, W[1], B[1], out);
    } else {
        prep_kernel<<<10, 256>>>(W[0], W[1], W5, b5);
        conv_kernel<<<512, 256>>>(x);
        zero_kernel<<<1024, 256>>>();
        edge_scatter_kernel<<<(Mm * 2 + 255) / 256, 256>>>(ef, esrc, edst, etype);
        h2_gemm_kernel<<<296, 256, h2_smem>>>(ntype, B[1]);
        h1_gemm_kernel<<<296, 256, h1_smem>>>(ntype, B[0], out);
        gatherH_kernel<<<(Nn + 31) / 32, 256>>>(out);
        ovf_kernel<<<8, 256>>>(x, ntype, W[1], B[1], out);
    }
}

// round 16
// speedup vs baseline: 1.1882x; 1.0554x over previous
#include <cuda_runtime.h>
#include <cuda_fp16.h>
#include <cstdint>

#define Nn 100000
#define Mm 800000
#define CAP 48

// ---------------- device scratch (no allocations allowed) ----------------
__device__ __half    g_h2h[(size_t)Nn * 64];    // h2 rows fp16 (identity word order)
__device__ __half    g_xh[(size_t)Nn * 64];     // x rows fp16 (identity word order)
__device__ uint32_t  g_aggEh[(size_t)Nn * 32];  // fp16 aggE rows; words 24..31 pad
__device__ int       g_cur[Nn];                 // packed: tot(10)|c1(10)|c2(10)
__device__ int       g_slots[(size_t)Nn * CAP]; // src node per bucket slot
__device__ int       g_ovf_cnt;
__device__ int2      g_ovf[8192];               // overflow: (src, dst)
__device__ uint4     g_Wf1[1536];               // h1 B fragments (W1|W5|b5)
__device__ uint4     g_Wf2[1024];               // h2 B fragments (W2)

__device__ __forceinline__ void red_add_h8(uint32_t* p, uint32_t a, uint32_t b,
                                           uint32_t c, uint32_t d) {
    asm volatile("red.global.add.noftz.v4.f16x2 [%0], {%1,%2,%3,%4};"
                 :: "l"(p), "r"(a), "r"(b), "r"(c), "r"(d) : "memory");
}

__device__ __forceinline__ void mma_f16(float c[4], uint32_t a0, uint32_t a1,
                                        uint32_t a2, uint32_t a3,
                                        uint32_t b0, uint32_t b1) {
    asm volatile(
        "mma.sync.aligned.m16n8k16.row.col.f32.f16.f16.f32 "
        "{%0,%1,%2,%3},{%4,%5,%6,%7},{%8,%9},{%0,%1,%2,%3};"
        : "+f"(c[0]), "+f"(c[1]), "+f"(c[2]), "+f"(c[3])
        : "r"(a0), "r"(a1), "r"(a2), "r"(a3), "r"(b0), "r"(b1));
}

__device__ __forceinline__ uint32_t pack_h2(float a, float b) {
    __half2 h = __floats2half2_rn(a, b);
    return *(uint32_t*)&h;
}

// ---------------- kernels ----------------

// init = prep (B fragments) + conv (x -> fp16) + zero (aggE, cursors)
__global__ void init_kernel(const float* __restrict__ x,
                            const float* __restrict__ W1,
                            const float* __restrict__ W2,
                            const float* __restrict__ W5,
                            const float* __restrict__ b5) {
    int gid = blockIdx.x * blockDim.x + threadIdx.x;
    int stride = gridDim.x * blockDim.x;

    // B fragments for h1 (W1 | W5 | b5), slot mapping:
    // slot p: word(p,h) = 16*(p>>1) + 4*tqf + 2*(p&1) + h; x col = 2*wd + elem
    for (int idx = gid; idx < 1536; idx += stride) {
        int ln = idx & 31;
        int ntp = (idx >> 5) & 3;
        int kb = idx >> 7;                    // 0..11
        int tqf = ln & 3, gf = ln >> 2;
        int col0 = (2 * ntp) * 8 + gf;
        int col1 = col0 + 8;
        auto val = [&](int h, int elem, int outc) -> float {
            if (kb < 8) {
                int ty = kb >> 2, p = kb & 3;
                int wd = 16 * (p >> 1) + 4 * tqf + 2 * (p & 1) + h;
                int hh = 2 * wd + elem;
                return W1[(size_t)ty * 4096 + hh * 64 + outc];
            } else {
                int p = kb - 8;
                int wd = 16 * (p >> 1) + 4 * tqf + 2 * (p & 1) + h;
                if (wd < 24) {
                    int t = wd >> 3, colf = 2 * (wd & 7) + elem;
                    return W5[(size_t)(t * 16 + colf) * 64 + outc];
                }
                if (wd == 24) return b5[elem * 64 + outc];
                if (wd == 25) return (elem == 0) ? b5[128 + outc] : 0.f;
                return 0.f;
            }
        };
        uint4 wv;
        wv.x = pack_h2(val(0, 0, col0), val(0, 1, col0));
        wv.y = pack_h2(val(1, 0, col0), val(1, 1, col0));
        wv.z = pack_h2(val(0, 0, col1), val(0, 1, col1));
        wv.w = pack_h2(val(1, 0, col1), val(1, 1, col1));
        g_Wf1[idx] = wv;
    }
    // B fragments for h2 (W2, both types)
    for (int idx = gid; idx < 1024; idx += stride) {
        int ln = idx & 31;
        int ntp = (idx >> 5) & 3;
        int kb = idx >> 7;                    // 0..7
        int tqf = ln & 3, gf = ln >> 2;
        int col0 = (2 * ntp) * 8 + gf;
        int col1 = col0 + 8;
        auto val2 = [&](int h, int elem, int outc) -> float {
            int ty = kb >> 2, p = kb & 3;
            int wd = 16 * (p >> 1) + 4 * tqf + 2 * (p & 1) + h;
            int hh = 2 * wd + elem;
            return W2[(size_t)ty * 4096 + hh * 64 + outc];
        };
        uint4 wv;
        wv.x = pack_h2(val2(0, 0, col0), val2(0, 1, col0));
        wv.y = pack_h2(val2(1, 0, col0), val2(1, 1, col0));
        wv.z = pack_h2(val2(0, 0, col1), val2(0, 1, col1));
        wv.w = pack_h2(val2(1, 0, col1), val2(1, 1, col1));
        g_Wf2[idx] = wv;
    }
    // x -> fp16
    const float4* x4 = (const float4*)x;
    uint2* xo = (uint2*)g_xh;
    for (int i = gid; i < Nn * 16; i += stride) {
        float4 f = x4[i];
        xo[i] = make_uint2(pack_h2(f.x, f.y), pack_h2(f.z, f.w));
    }
    // zero aggE + cursors
    uint4 z = make_uint4(0u, 0u, 0u, 0u);
    uint4* a4 = (uint4*)g_aggEh;
    for (int i = gid; i < Nn * 8; i += stride) a4[i] = z;
    for (int i = gid; i < Nn; i += stride) g_cur[i] = 0;
    if (gid == 0) g_ovf_cnt = 0;
}

// 2 threads/edge: fp16x8 red into aggE row + packed cursor + bucket fill
__global__ void edge_scatter_kernel(const float* __restrict__ ef,
                                    const int* __restrict__ esrc,
                                    const int* __restrict__ edst,
                                    const int* __restrict__ etype) {
    int gid = blockIdx.x * blockDim.x + threadIdx.x;
    int e = gid >> 1, q = gid & 1;
    if (e >= Mm) return;
    int dst = edst[e];
    int t   = etype[e];
    const float4* ef4 = (const float4*)ef;
    float4 v0 = ef4[e * 4 + q * 2];
    float4 v1 = ef4[e * 4 + q * 2 + 1];
    uint32_t h0 = pack_h2(v0.x, v0.y), h1 = pack_h2(v0.z, v0.w);
    uint32_t h2 = pack_h2(v1.x, v1.y), h3 = pack_h2(v1.z, v1.w);
    red_add_h8(g_aggEh + (size_t)dst * 32 + t * 8 + q * 4, h0, h1, h2, h3);
    if (q == 0) {
        int inc = 1 + ((t == 1) ? (1 << 10) : 0) + ((t == 2) ? (1 << 20) : 0);
        int old = atomicAdd(&g_cur[dst], inc);
        int p = old & 1023;
        int src = esrc[e];
        if (p < CAP) {
            g_slots[(size_t)dst * CAP + p] = src;
        } else {
            int o = atomicAdd(&g_ovf_cnt, 1);
            if (o < 8192) g_ovf[o] = make_int2(src, dst);
        }
    }
}

// Fused GEMM: one pass over nodes. Phase A (8 kb, W2) -> h2h; Phase B
// (12 kb, W1|W5|b5, x masked + tail) -> out (FULL write). x fragments shared.
__global__ __launch_bounds__(256, 2)
void fused_gemm_kernel(const int* __restrict__ ntype,
                       const float* __restrict__ b1,
                       const float* __restrict__ b2,
                       float* __restrict__ out) {
    extern __shared__ uint32_t smu[];
    uint4* Wf2 = (uint4*)smu;                 // 1024 uint4 = 16 KB
    uint4* Wf1 = Wf2 + 1024;                  // 1536 uint4 = 24 KB
    float* bc2 = (float*)(Wf1 + 1536);        // [128]
    float* bc1 = bc2 + 128;                   // [128]

    const int tid = threadIdx.x;
    const int w = tid >> 5, lane = tid & 31;
    const int g = lane >> 2, tq = lane & 3;

    for (int idx = tid; idx < 1024; idx += 256) Wf2[idx] = g_Wf2[idx];
    for (int idx = tid; idx < 1536; idx += 256) Wf1[idx] = g_Wf1[idx];
    if (tid < 128) { bc2[tid] = b2[tid]; bc1[tid] = b1[tid]; }
    __syncthreads();

    const int G = Nn >> 4;
    const int nwarps = gridDim.x << 3;
    __half2* h2p = (__half2*)g_h2h;
    float2* outp = (float2*)out;
    const uint4* xh4 = (const uint4*)g_xh;
    const uint4* ag4 = (const uint4*)g_aggEh;

    for (int grp = blockIdx.x * 8 + w; grp < G; grp += nwarps) {
        int base = grp << 4;
        uint4 xu[2][2], tu[2][2];
        uint32_t msk[2];
        int tt[2];
        #pragma unroll
        for (int j = 0; j < 2; j++) {
            int node = base + g + 8 * j;
            tt[j] = __ldg(&ntype[node]);
            msk[j] = (tt[j] == 0) ? 0xFFFFFFFFu : 0u;
            xu[j][0] = __ldg(&xh4[(size_t)node * 8 + tq]);
            xu[j][1] = __ldg(&xh4[(size_t)node * 8 + tq + 4]);
            tu[j][0] = __ldg(&ag4[(size_t)node * 8 + tq]);
            tu[j][1] = __ldg(&ag4[(size_t)node * 8 + tq + 4]);
            int cv = __ldg(&g_cur[node]);
            if (tq == 2) {
                int tot = cv & 1023, c1i = (cv >> 10) & 1023, c2i = cv >> 20;
                tu[j][1].x = pack_h2((float)(tot - c1i - c2i), (float)c1i);
                tu[j][1].y = pack_h2((float)c2i, 0.f);
            }
        }

        auto slot = [&](uint4 uq[2], int p, int h) -> uint32_t {
            uint4 uu = uq[p >> 1];
            return (p & 1) ? (h ? uu.w : uu.z) : (h ? uu.y : uu.x);
        };

        float acc[8][4];

        // ---- phase A: h2 = W2-GEMM -> h2h ----
        #pragma unroll
        for (int nt = 0; nt < 8; nt++)
            #pragma unroll
            for (int jj = 0; jj < 4; jj++) acc[nt][jj] = 0.f;

        #pragma unroll
        for (int kb = 0; kb < 8; kb++) {
            int p = kb & 3;
            uint32_t s0 = (kb < 4) ? msk[0] : ~msk[0];
            uint32_t s1 = (kb < 4) ? msk[1] : ~msk[1];
            uint32_t a0 = slot(xu[0], p, 0) & s0;
            uint32_t a2 = slot(xu[0], p, 1) & s0;
            uint32_t a1 = slot(xu[1], p, 0) & s1;
            uint32_t a3 = slot(xu[1], p, 1) & s1;
            #pragma unroll
            for (int ntp = 0; ntp < 4; ntp++) {
                uint4 bw = Wf2[(kb * 4 + ntp) * 32 + lane];
                mma_f16(acc[2 * ntp], a0, a1, a2, a3, bw.x, bw.y);
                mma_f16(acc[2 * ntp + 1], a0, a1, a2, a3, bw.z, bw.w);
            }
        }
        #pragma unroll
        for (int j = 0; j < 2; j++) {
            int node = base + g + 8 * j;
            int t = tt[j];
            #pragma unroll
            for (int nt = 0; nt < 8; nt++) {
                int col0 = nt * 8 + 2 * tq;
                float v0 = acc[nt][2 * j + 0] + bc2[t * 64 + col0];
                float v1 = acc[nt][2 * j + 1] + bc2[t * 64 + col0 + 1];
                h2p[(size_t)node * 32 + nt * 4 + tq] = __floats2half2_rn(v0, v1);
            }
        }

        // ---- phase B: h1 = (W1|W5|b5)-GEMM -> out ----
        #pragma unroll
        for (int nt = 0; nt < 8; nt++)
            #pragma unroll
            for (int jj = 0; jj < 4; jj++) acc[nt][jj] = 0.f;

        #pragma unroll
        for (int kb = 0; kb < 12; kb++) {
            uint32_t a0, a1, a2, a3;
            if (kb < 8) {
                int p = kb & 3;
                uint32_t s0 = (kb < 4) ? msk[0] : ~msk[0];
                uint32_t s1 = (kb < 4) ? msk[1] : ~msk[1];
                a0 = slot(xu[0], p, 0) & s0;
                a2 = slot(xu[0], p, 1) & s0;
                a1 = slot(xu[1], p, 0) & s1;
                a3 = slot(xu[1], p, 1) & s1;
            } else {
                int p = kb - 8;
                a0 = slot(tu[0], p, 0); a2 = slot(tu[0], p, 1);
                a1 = slot(tu[1], p, 0); a3 = slot(tu[1], p, 1);
            }
            #pragma unroll
            for (int ntp = 0; ntp < 4; ntp++) {
                uint4 bw = Wf1[(kb * 4 + ntp) * 32 + lane];
                mma_f16(acc[2 * ntp], a0, a1, a2, a3, bw.x, bw.y);
                mma_f16(acc[2 * ntp + 1], a0, a1, a2, a3, bw.z, bw.w);
            }
        }
        #pragma unroll
        for (int j = 0; j < 2; j++) {
            int node = base + g + 8 * j;
            int t = tt[j];
            #pragma unroll
            for (int nt = 0; nt < 8; nt++) {
                int col0 = nt * 8 + 2 * tq;
                float v0 = acc[nt][2 * j + 0] + bc1[t * 64 + col0];
                float v1 = acc[nt][2 * j + 1] + bc1[t * 64 + col0 + 1];
                outp[(size_t)node * 32 + nt * 4 + tq] = make_float2(v0, v1);
            }
        }
    }
}

// Bucket gather: out[dst] += sum h2h[src]; 8 lanes/node; slots via uint4.
// Overflow edges (deg > CAP) handled inline: their contribution IS h2h[src],
// so the owning node scans the (normally empty) g_ovf list.
__global__ __launch_bounds__(256)
void gatherH_kernel(float* __restrict__ out) {
    int tid = threadIdx.x;
    int node = blockIdx.x * 32 + (tid >> 3);
    int q = tid & 7;
    if (node >= Nn) return;
    int deg_raw = g_cur[node] & 1023;
    int deg = (deg_raw > CAP) ? CAP : deg_raw;
    if (deg == 0) return;

    const uint4* H = (const uint4*)g_h2h;
    const int* sl = &g_slots[(size_t)node * CAP];
    const uint4* sl4 = (const uint4*)sl;
    float acc[8];
    #pragma unroll
    for (int u = 0; u < 8; u++) acc[u] = 0.f;

    auto add8 = [&](uint4 hv) {
        float2 f0 = __half22float2(*(__half2*)&hv.x);
        float2 f1 = __half22float2(*(__half2*)&hv.y);
        float2 f2 = __half22float2(*(__half2*)&hv.z);
        float2 f3 = __half22float2(*(__half2*)&hv.w);
        acc[0] += f0.x; acc[1] += f0.y; acc[2] += f1.x; acc[3] += f1.y;
        acc[4] += f2.x; acc[5] += f2.y; acc[6] += f3.x; acc[7] += f3.y;
    };

    int i = 0;
    for (; i + 8 <= deg; i += 8) {
        uint4 sa = __ldg(&sl4[i >> 2]);
        uint4 sb = __ldg(&sl4[(i >> 2) + 1]);
        uint4 v0 = __ldg(&H[(size_t)sa.x * 8 + q]);
        uint4 v1 = __ldg(&H[(size_t)sa.y * 8 + q]);
        uint4 v2 = __ldg(&H[(size_t)sa.z * 8 + q]);
        uint4 v3 = __ldg(&H[(size_t)sa.w * 8 + q]);
        uint4 v4 = __ldg(&H[(size_t)sb.x * 8 + q]);
        uint4 v5 = __ldg(&H[(size_t)sb.y * 8 + q]);
        uint4 v6 = __ldg(&H[(size_t)sb.z * 8 + q]);
        uint4 v7 = __ldg(&H[(size_t)sb.w * 8 + q]);
        add8(v0); add8(v1); add8(v2); add8(v3);
        add8(v4); add8(v5); add8(v6); add8(v7);
    }
    for (; i + 4 <= deg; i += 4) {
        uint4 sa = __ldg(&sl4[i >> 2]);
        uint4 v0 = __ldg(&H[(size_t)sa.x * 8 + q]);
        uint4 v1 = __ldg(&H[(size_t)sa.y * 8 + q]);
        uint4 v2 = __ldg(&H[(size_t)sa.z * 8 + q]);
        uint4 v3 = __ldg(&H[(size_t)sa.w * 8 + q]);
        add8(v0); add8(v1); add8(v2); add8(v3);
    }
    for (; i < deg; i++) add8(__ldg(&H[(size_t)__ldg(&sl[i]) * 8 + q]));

    if (deg_raw > CAP) {
        int n = g_ovf_cnt;
        if (n > 8192) n = 8192;
        for (int oi = 0; oi < n; oi++) {
            int2 sd = g_ovf[oi];
            if (sd.y == node) add8(__ldg(&H[(size_t)sd.x * 8 + q]));
        }
    }

    float4* o4 = (float4*)out;
    float4 oa = o4[(size_t)node * 16 + 2 * q];
    float4 ob = o4[(size_t)node * 16 + 2 * q + 1];
    oa.x += acc[0]; oa.y += acc[1]; oa.z += acc[2]; oa.w += acc[3];
    ob.x += acc[4]; ob.y += acc[5]; ob.z += acc[6]; ob.w += acc[7];
    o4[(size_t)node * 16 + 2 * q] = oa;
    o4[(size_t)node * 16 + 2 * q + 1] = ob;
}

// ---------------- launch ----------------
extern "C" void kernel_launch(void* const* d_in, const int* in_sizes, int n_in,
                              void* d_out, int out_size) {
    const float *x = nullptr, *ef = nullptr;
    const float *W[4] = {nullptr, nullptr, nullptr, nullptr};
    const float *B[4] = {nullptr, nullptr, nullptr, nullptr};
    const float *W5 = nullptr, *b5 = nullptr;
    const int *ntype = nullptr, *esrc = nullptr, *edst = nullptr, *etype = nullptr;
    int wI = 0, bI = 0, mI = 0;
    for (int i = 0; i < n_in; i++) {
        long s = in_sizes[i];
        const void* p = d_in[i];
        if (s == (long)Nn * 64)       x = (const float*)p;
        else if (s == (long)Mm * 16)  ef = (const float*)p;
        else if (s == Nn)             ntype = (const int*)p;
        else if (s == Mm) {
            if (mI == 0) esrc = (const int*)p;
            else if (mI == 1) edst = (const int*)p;
            else etype = (const int*)p;
            mI++;
        }
        else if (s == 2 * 64 * 64) { if (wI < 4) W[wI++] = (const float*)p; }
        else if (s == 2 * 64)      { if (bI < 4) B[bI++] = (const float*)p; }
        else if (s == 3 * 16 * 64) W5 = (const float*)p;
        else if (s == 3 * 64)      b5 = (const float*)p;
    }
    float* out = (float*)d_out;

    const int gemm_smem = 2560 * 16 + 256 * 4;   // 41984
    cudaFuncSetAttribute(fused_gemm_kernel,
                         cudaFuncAttributeMaxDynamicSharedMemorySize, 48 * 1024);

    init_kernel<<<2048, 256>>>(x, W[0], W[1], W5, b5);
    edge_scatter_kernel<<<(Mm * 2 + 255) / 256, 256>>>(ef, esrc, edst, etype);
    fused_gemm_kernel<<<296, 256, gemm_smem>>>(ntype, B[0], B[1], out);
    gatherH_kernel<<<(Nn + 31) / 32, 256>>>(out);
}